// round 9
// baseline (speedup 1.0000x reference)
#include <cuda_runtime.h>
#include <cuda_bf16.h>
#include <cstddef>
#include <cstdint>

// SparseConv: out[out_map[k,m]] += x[in_map[k,m]] @ W[k]   (K=27, M=65536, Cin=Cout=64)
//
// Round 9: A fragments loaded DIRECTLY from global (no smem staging for A):
//   m16n8k16 A-fragment = 4x LDG.64 per lane (sector-coalesced per 4-lane group),
//   fp32 -> bf16 hi/lo split in registers. Kills STS-A, LDSM-A and all per-tile
//   barriers (main loop is barrier-free; B staged in smem once per CTA).
//   Index loads for tile t+1 prefetched into registers during tile t.
//   3 CTAs/SM (launch_bounds 256,3), grid (16,27).

#define CIN     64
#define COUT    64
#define THREADS 256
#define CTAS_X  16

#define STRIDE_B 144
#define SM_B_HI  0
#define SM_B_LO  (CIN * STRIDE_B)            // 9216
#define SM_TOTAL (2 * CIN * STRIDE_B)        // 18432 B

__device__ __forceinline__ uint32_t smem_u32(const void* p) {
    uint32_t a;
    asm("{ .reg .u64 t; cvta.to.shared.u64 t, %1; cvt.u32.u64 %0, t; }" : "=r"(a) : "l"(p));
    return a;
}
__device__ __forceinline__ uint32_t pack_bf16x2(float hi_elem, float lo_elem) {
    uint32_t r;
    asm("cvt.rn.bf16x2.f32 %0, %1, %2;" : "=r"(r) : "f"(hi_elem), "f"(lo_elem));
    return r;  // [15:0]=bf16(lo_elem), [31:16]=bf16(hi_elem)
}
// split float2 into packed bf16 hi pair + residual lo pair
__device__ __forceinline__ void split2(float2 v, uint32_t& hi, uint32_t& lo) {
    hi = pack_bf16x2(v.y, v.x);
    const float r0 = v.x - __uint_as_float(hi << 16);
    const float r1 = v.y - __uint_as_float(hi & 0xFFFF0000u);
    lo = pack_bf16x2(r1, r0);
}

#define LDSM_X4_T(r, addr) \
    asm volatile("ldmatrix.sync.aligned.m8n8.x4.trans.shared.b16 {%0,%1,%2,%3}, [%4];" \
        : "=r"((r)[0]), "=r"((r)[1]), "=r"((r)[2]), "=r"((r)[3]) : "r"(addr))

#define MMA_BF16(c, a, b0, b1) \
    asm volatile("mma.sync.aligned.m16n8k16.row.col.f32.bf16.bf16.f32 " \
        "{%0,%1,%2,%3}, {%4,%5,%6,%7}, {%8,%9}, {%0,%1,%2,%3};" \
        : "+f"((c)[0]), "+f"((c)[1]), "+f"((c)[2]), "+f"((c)[3]) \
        : "r"((a)[0]), "r"((a)[1]), "r"((a)[2]), "r"((a)[3]), "r"(b0), "r"(b1))

__device__ __forceinline__ void red_add_v4(float* dst, float a, float b, float c, float d) {
    asm volatile("red.global.add.v4.f32 [%0], {%1, %2, %3, %4};"
                 :: "l"(dst), "f"(a), "f"(b), "f"(c), "f"(d) : "memory");
}

__global__ void __launch_bounds__(THREADS, 3) sparse_conv_mma6(
    const float* __restrict__ x,
    const float* __restrict__ W,
    const int*   __restrict__ in_map,
    const int*   __restrict__ out_map,
    float*       __restrict__ out,
    int M)
{
    extern __shared__ char smem[];
    const uint32_t sb = smem_u32(smem);
    const int tid  = threadIdx.x;
    const int w    = tid >> 5;
    const int lane = tid & 31;
    const int mg   = w >> 1;        // row group: rows 32*mg .. 32*mg+31
    const int nh   = w & 1;         // col half:  cols 32*nh .. 32*nh+31
    const int k    = blockIdx.y;
    const int kM   = k * M;
    const int ntiles = M >> 7;

    // --- stage W[k] -> bf16 hi/lo in smem (once per CTA) ---
    {
        const float* Wk = W + (size_t)k * (CIN * COUT);
        #pragma unroll
        for (int i = 0; i < (CIN * COUT) / THREADS; i++) {
            const int lin = tid + i * THREADS;
            const int c = lin >> 6, n = lin & 63;
            const float wv = Wk[lin];
            const __nv_bfloat16 hv = __float2bfloat16(wv);
            const __nv_bfloat16 lv = __float2bfloat16(wv - __bfloat162float(hv));
            const uint32_t off = (uint32_t)(c * STRIDE_B + n * 2);
            *(__nv_bfloat16*)(smem + SM_B_HI + off) = hv;
            *(__nv_bfloat16*)(smem + SM_B_LO + off) = lv;
        }
    }
    __syncthreads();   // the ONLY barrier; main loop is barrier-free

    // B ldmatrix addressing (identical to R8)
    const uint32_t b_off = (uint32_t)((lane & 15) * STRIDE_B + (lane >> 4) * 16 + nh * 64);
    const uint32_t bHi = sb + SM_B_HI + b_off;
    const uint32_t bLo = sb + SM_B_LO + b_off;

    // A fragment lane geometry
    const int g  = lane >> 2;            // row within 8-row group
    const int c2 = (lane & 3) * 2;       // col pair base
    const int rA0 = 32 * mg + g;         // t=0 upper row
    // rows needed: rA0, rA0+8 (t=0); rA0+16, rA0+24 (t=1)

    // epilogue lane mapping
    const bool odd = (lane & 1);
    const int  er0 = 32 * mg + (lane >> 2) + (odd ? 8 : 0);
    const int  q0  = (lane & 2) * 2;

    // --- prime index registers for first tile ---
    int mt = blockIdx.x;
    int iA0, iB0, iA1, iB1, or0, or1;
    {
        const int base = kM + (mt << 7);
        iA0 = in_map[base + rA0];
        iB0 = in_map[base + rA0 + 8];
        iA1 = in_map[base + rA0 + 16];
        iB1 = in_map[base + rA0 + 24];
        or0 = out_map[base + er0];
        or1 = out_map[base + er0 + 16];
    }

    while (mt < ntiles) {
        const int nxt = mt + CTAS_X;

        // prefetch next tile's indices (in flight during this tile's loads+MMA)
        int nA0 = 0, nB0 = 0, nA1 = 0, nB1 = 0, no0 = 0, no1 = 0;
        if (nxt < ntiles) {
            const int base = kM + (nxt << 7);
            nA0 = in_map[base + rA0];
            nB0 = in_map[base + rA0 + 8];
            nA1 = in_map[base + rA0 + 16];
            nB1 = in_map[base + rA0 + 24];
            no0 = out_map[base + er0];
            no1 = out_map[base + er0 + 16];
        }

        const float* pA0 = x + (size_t)iA0 * CIN + c2;
        const float* pB0 = x + (size_t)iB0 * CIN + c2;
        const float* pA1 = x + (size_t)iA1 * CIN + c2;
        const float* pB1 = x + (size_t)iB1 * CIN + c2;

        float acc[2][4][4];
        #pragma unroll
        for (int t = 0; t < 2; t++)
            #pragma unroll
            for (int j = 0; j < 4; j++)
                #pragma unroll
                for (int i = 0; i < 4; i++) acc[t][j][i] = 0.0f;

        #pragma unroll
        for (int s = 0; s < 4; s++) {
            // B fragments for this k-step (hi + lo, both 16-col halves)
            uint32_t bh[2][4], bl[2][4];
            const uint32_t so = (uint32_t)(s * 16 * STRIDE_B);
            LDSM_X4_T(bh[0], bHi + so);
            LDSM_X4_T(bh[1], bHi + so + 32);
            LDSM_X4_T(bl[0], bLo + so);
            LDSM_X4_T(bl[1], bLo + so + 32);

            const int sc = s * 16;
            #pragma unroll
            for (int t = 0; t < 2; t++) {
                // A fragment: 4x LDG.64 straight from x
                const float* pa = t ? pA1 : pA0;
                const float* pb = t ? pB1 : pB0;
                const float2 v0 = *(const float2*)(pa + sc);
                const float2 v1 = *(const float2*)(pb + sc);
                const float2 v2 = *(const float2*)(pa + sc + 8);
                const float2 v3 = *(const float2*)(pb + sc + 8);
                uint32_t ah[4], al[4];
                split2(v0, ah[0], al[0]);
                split2(v1, ah[1], al[1]);
                split2(v2, ah[2], al[2]);
                split2(v3, ah[3], al[3]);
                #pragma unroll
                for (int p = 0; p < 2; p++) {
                    MMA_BF16(acc[t][2 * p],     ah, bh[p][0], bh[p][1]);
                    MMA_BF16(acc[t][2 * p + 1], ah, bh[p][2], bh[p][3]);
                    MMA_BF16(acc[t][2 * p],     ah, bl[p][0], bl[p][1]);
                    MMA_BF16(acc[t][2 * p + 1], ah, bl[p][2], bl[p][3]);
                    MMA_BF16(acc[t][2 * p],     al, bh[p][0], bh[p][1]);
                    MMA_BF16(acc[t][2 * p + 1], al, bh[p][2], bh[p][3]);
                }
            }
        }

        // --- epilogue: shfl pair-swap -> red.global.add.v4 ---
        #pragma unroll
        for (int t = 0; t < 2; t++) {
            const int orow = t ? or1 : or0;
            float* obase = out + (size_t)orow * COUT + nh * 32 + q0;
            #pragma unroll
            for (int j = 0; j < 4; j++) {
                float* c = acc[t][j];
                const float s0 = __shfl_xor_sync(0xFFFFFFFFu, c[0], 1);
                const float s1 = __shfl_xor_sync(0xFFFFFFFFu, c[1], 1);
                const float s2 = __shfl_xor_sync(0xFFFFFFFFu, c[2], 1);
                const float s3 = __shfl_xor_sync(0xFFFFFFFFu, c[3], 1);
                const float v0 = odd ? s2 : c[0];
                const float v1 = odd ? s3 : c[1];
                const float v2 = odd ? c[2] : s0;
                const float v3 = odd ? c[3] : s1;
                red_add_v4(obase + 8 * j, v0, v1, v2, v3);
            }
        }

        iA0 = nA0; iB0 = nB0; iA1 = nA1; iB1 = nB1; or0 = no0; or1 = no1;
        mt = nxt;
    }
}

extern "C" void kernel_launch(void* const* d_in, const int* in_sizes, int n_in,
                              void* d_out, int out_size)
{
    const float* x       = (const float*)d_in[0];
    const float* W       = (const float*)d_in[1];
    const int*   in_map  = (const int*)d_in[2];
    const int*   out_map = (const int*)d_in[3];
    float*       out     = (float*)d_out;

    const int K = in_sizes[1] / (CIN * COUT);   // 27
    const int M = in_sizes[2] / K;              // 65536

    cudaMemsetAsync(d_out, 0, (size_t)out_size * sizeof(float), 0);

    dim3 grid(CTAS_X, K);
    sparse_conv_mma6<<<grid, THREADS, SM_TOTAL>>>(x, W, in_map, out_map, out, M);
}

// round 10
// speedup vs baseline: 1.2019x; 1.2019x over previous
#include <cuda_runtime.h>
#include <cuda_bf16.h>
#include <cstddef>
#include <cstdint>

// SparseConv: out[out_map[k,m]] += x[in_map[k,m]] @ W[k]   (K=27, M=65536, Cin=Cout=64)
//
// Round 10: R8 base (227.5us) with the A-path moved off L1:
//   - pre-pass kernel splits x fp32 -> global bf16 hi/lo planes (__device__ scratch)
//   - per-tile A gather = cp.async.cg 16B chunks (global->smem, no RF/L1 round trip,
//     no in-loop cvt, no STS)
//   - MMA / LDSM / RED epilogue identical to R8; occ 3 (launch_bounds 256,3)

#define CIN     64
#define COUT    64
#define THREADS 256
#define CTAS_X  16

#define STRIDE_A 144
#define STRIDE_B 144

#define ABUF     (128 * STRIDE_A)            // 18432 B per hi/lo plane
#define SM_A_HI  0
#define SM_A_LO  ABUF                        // 18432
#define SM_B_HI  (2 * ABUF)                  // 36864
#define SM_B_LO  (SM_B_HI + CIN * STRIDE_B)  // 46080
#define SM_TOTAL (SM_B_LO + CIN * STRIDE_B)  // 55296 B -> 3 CTAs/SM

// global scratch: bf16 hi/lo planes of x, row-major 64 cols (128 B rows), as uint2 chunks
#define NMAX_CHUNK (262144 * 16)             // 262144 rows * 16 uint2 (8B) per row
__device__ __align__(16) uint2 g_xhi[NMAX_CHUNK];
__device__ __align__(16) uint2 g_xlo[NMAX_CHUNK];

__device__ __forceinline__ uint32_t smem_u32(const void* p) {
    uint32_t a;
    asm("{ .reg .u64 t; cvta.to.shared.u64 t, %1; cvt.u32.u64 %0, t; }" : "=r"(a) : "l"(p));
    return a;
}
__device__ __forceinline__ uint32_t pack_bf16x2(float hi_elem, float lo_elem) {
    uint32_t r;
    asm("cvt.rn.bf16x2.f32 %0, %1, %2;" : "=r"(r) : "f"(hi_elem), "f"(lo_elem));
    return r;  // [15:0]=bf16(lo_elem), [31:16]=bf16(hi_elem)
}

#define CP_ASYNC16(dst, src) \
    asm volatile("cp.async.cg.shared.global [%0], [%1], 16;" :: "r"(dst), "l"(src) : "memory")
#define CP_COMMIT()  asm volatile("cp.async.commit_group;" ::: "memory")
#define CP_WAIT0()   asm volatile("cp.async.wait_group 0;" ::: "memory")

#define LDSM_X4(r, addr) \
    asm volatile("ldmatrix.sync.aligned.m8n8.x4.shared.b16 {%0,%1,%2,%3}, [%4];" \
        : "=r"((r)[0]), "=r"((r)[1]), "=r"((r)[2]), "=r"((r)[3]) : "r"(addr))

#define LDSM_X4_T(r, addr) \
    asm volatile("ldmatrix.sync.aligned.m8n8.x4.trans.shared.b16 {%0,%1,%2,%3}, [%4];" \
        : "=r"((r)[0]), "=r"((r)[1]), "=r"((r)[2]), "=r"((r)[3]) : "r"(addr))

#define MMA_BF16(c, a, b0, b1) \
    asm volatile("mma.sync.aligned.m16n8k16.row.col.f32.bf16.bf16.f32 " \
        "{%0,%1,%2,%3}, {%4,%5,%6,%7}, {%8,%9}, {%0,%1,%2,%3};" \
        : "+f"((c)[0]), "+f"((c)[1]), "+f"((c)[2]), "+f"((c)[3]) \
        : "r"((a)[0]), "r"((a)[1]), "r"((a)[2]), "r"((a)[3]), "r"(b0), "r"(b1))

__device__ __forceinline__ void red_add_v4(float* dst, float a, float b, float c, float d) {
    asm volatile("red.global.add.v4.f32 [%0], {%1, %2, %3, %4};"
                 :: "l"(dst), "f"(a), "f"(b), "f"(c), "f"(d) : "memory");
}

// ---------- pre-pass: x fp32 -> bf16 hi/lo planes ----------
__global__ void __launch_bounds__(256) split_x_kernel(const float* __restrict__ x, int total4)
{
    const int i = blockIdx.x * 256 + threadIdx.x;
    if (i >= total4) return;
    const float4 v = ((const float4*)x)[i];
    const uint32_t h0 = pack_bf16x2(v.y, v.x);
    const uint32_t h1 = pack_bf16x2(v.w, v.z);
    const float r0 = v.x - __uint_as_float(h0 << 16);
    const float r1 = v.y - __uint_as_float(h0 & 0xFFFF0000u);
    const float r2 = v.z - __uint_as_float(h1 << 16);
    const float r3 = v.w - __uint_as_float(h1 & 0xFFFF0000u);
    g_xhi[i] = make_uint2(h0, h1);
    g_xlo[i] = make_uint2(pack_bf16x2(r1, r0), pack_bf16x2(r3, r2));
}

// ---------- main kernel ----------
__global__ void __launch_bounds__(THREADS, 3) sparse_conv_mma7(
    const float* __restrict__ W,
    const int*   __restrict__ in_map,
    const int*   __restrict__ out_map,
    float*       __restrict__ out,
    int M)
{
    extern __shared__ char smem[];
    const uint32_t sb = smem_u32(smem);
    const int tid  = threadIdx.x;
    const int w    = tid >> 5;
    const int lane = tid & 31;
    const int mg   = w >> 1;        // rows 32*mg .. 32*mg+31
    const int nh   = w & 1;         // cols 32*nh .. 32*nh+31
    const int k    = blockIdx.y;
    const int kM   = k * M;
    const int ntiles = M >> 7;

    // --- stage W[k] -> bf16 hi/lo in smem (once per CTA) ---
    {
        const float* Wk = W + (size_t)k * (CIN * COUT);
        #pragma unroll
        for (int i = 0; i < (CIN * COUT) / THREADS; i++) {
            const int lin = tid + i * THREADS;
            const int c = lin >> 6, n = lin & 63;
            const float wv = Wk[lin];
            const __nv_bfloat16 hv = __float2bfloat16(wv);
            const __nv_bfloat16 lv = __float2bfloat16(wv - __bfloat162float(hv));
            const uint32_t off = (uint32_t)(c * STRIDE_B + n * 2);
            *(__nv_bfloat16*)(smem + SM_B_HI + off) = hv;
            *(__nv_bfloat16*)(smem + SM_B_LO + off) = lv;
        }
    }

    // fragment addressing (same as R8)
    const uint32_t b_off = (uint32_t)((lane & 15) * STRIDE_B + (lane >> 4) * 16 + nh * 64);
    const uint32_t bHi = sb + SM_B_HI + b_off;
    const uint32_t bLo = sb + SM_B_LO + b_off;
    const uint32_t a_off = (uint32_t)((32 * mg + (lane & 15)) * STRIDE_A + (lane >> 4) * 16);
    const uint32_t aHi = sb + SM_A_HI + a_off;
    const uint32_t aLo = sb + SM_A_LO + a_off;

    // epilogue lane mapping
    const bool odd = (lane & 1);
    const int  er0 = 32 * mg + (lane >> 2) + (odd ? 8 : 0);
    const int  q0  = (lane & 2) * 2;

    // gather chunk mapping: thread handles 4 (e,c) pairs, both planes each
    // f = tid + j*256, e = f>>3 (row 0..127), c = f&7 (16B chunk in 128B row)
    const char* xhiB = (const char*)g_xhi;
    const char* xloB = (const char*)g_xlo;

    for (int mt = blockIdx.x; mt < ntiles; mt += CTAS_X) {
        const int m0 = mt << 7;

        __syncthreads();   // previous tile's LDSM readers done before overwrite

        // --- A gather: cp.async.cg from pre-split planes ---
        #pragma unroll
        for (int j = 0; j < 4; j++) {
            const int f = tid + j * THREADS;
            const int e = f >> 3, c = f & 7;
            const int row = in_map[kM + m0 + e];
            const size_t sboff = (size_t)row * 128 + c * 16;
            const uint32_t doff = (uint32_t)(e * STRIDE_A + c * 16);
            CP_ASYNC16(sb + SM_A_HI + doff, xhiB + sboff);
            CP_ASYNC16(sb + SM_A_LO + doff, xloB + sboff);
        }
        CP_COMMIT();

        // epilogue rows prefetch (overlaps async copies)
        const int orow0 = out_map[kM + m0 + er0];
        const int orow1 = out_map[kM + m0 + er0 + 16];

        CP_WAIT0();
        __syncthreads();

        // --- MMA: s-outer; B hi+lo from smem once per s; t inner ---
        float acc[2][4][4];
        #pragma unroll
        for (int t = 0; t < 2; t++)
            #pragma unroll
            for (int j = 0; j < 4; j++)
                #pragma unroll
                for (int i = 0; i < 4; i++) acc[t][j][i] = 0.0f;

        #pragma unroll
        for (int s = 0; s < 4; s++) {
            uint32_t bh[2][4], bl[2][4];
            const uint32_t so = (uint32_t)(s * 16 * STRIDE_B);
            LDSM_X4_T(bh[0], bHi + so);
            LDSM_X4_T(bh[1], bHi + so + 32);
            LDSM_X4_T(bl[0], bLo + so);
            LDSM_X4_T(bl[1], bLo + so + 32);
            #pragma unroll
            for (int t = 0; t < 2; t++) {
                uint32_t ah[4], al[4];
                const uint32_t ao = (uint32_t)(t * 16 * STRIDE_A + s * 32);
                LDSM_X4(ah, aHi + ao);
                LDSM_X4(al, aLo + ao);
                #pragma unroll
                for (int p = 0; p < 2; p++) {
                    MMA_BF16(acc[t][2 * p],     ah, bh[p][0], bh[p][1]);
                    MMA_BF16(acc[t][2 * p + 1], ah, bh[p][2], bh[p][3]);
                    MMA_BF16(acc[t][2 * p],     ah, bl[p][0], bl[p][1]);
                    MMA_BF16(acc[t][2 * p + 1], ah, bl[p][2], bl[p][3]);
                    MMA_BF16(acc[t][2 * p],     al, bh[p][0], bh[p][1]);
                    MMA_BF16(acc[t][2 * p + 1], al, bh[p][2], bh[p][3]);
                }
            }
        }

        // --- epilogue: shfl pair-swap -> red.global.add.v4 ---
        #pragma unroll
        for (int t = 0; t < 2; t++) {
            const int orow = t ? orow1 : orow0;
            float* obase = out + (size_t)orow * COUT + nh * 32 + q0;
            #pragma unroll
            for (int j = 0; j < 4; j++) {
                float* c = acc[t][j];
                const float s0 = __shfl_xor_sync(0xFFFFFFFFu, c[0], 1);
                const float s1 = __shfl_xor_sync(0xFFFFFFFFu, c[1], 1);
                const float s2 = __shfl_xor_sync(0xFFFFFFFFu, c[2], 1);
                const float s3 = __shfl_xor_sync(0xFFFFFFFFu, c[3], 1);
                const float v0 = odd ? s2 : c[0];
                const float v1 = odd ? s3 : c[1];
                const float v2 = odd ? c[2] : s0;
                const float v3 = odd ? c[3] : s1;
                red_add_v4(obase + 8 * j, v0, v1, v2, v3);
            }
        }
    }
}

extern "C" void kernel_launch(void* const* d_in, const int* in_sizes, int n_in,
                              void* d_out, int out_size)
{
    const float* x       = (const float*)d_in[0];
    const float* W       = (const float*)d_in[1];
    const int*   in_map  = (const int*)d_in[2];
    const int*   out_map = (const int*)d_in[3];
    float*       out     = (float*)d_out;

    const int K = in_sizes[1] / (CIN * COUT);   // 27
    const int M = in_sizes[2] / K;              // 65536
    const int total4 = in_sizes[0] / 4;         // N*64/4 float4 chunks

    static bool attr_set = false;
    if (!attr_set) {
        cudaFuncSetAttribute(sparse_conv_mma7,
                             cudaFuncAttributeMaxDynamicSharedMemorySize, SM_TOTAL);
        attr_set = true;
    }

    cudaMemsetAsync(d_out, 0, (size_t)out_size * sizeof(float), 0);
    split_x_kernel<<<(total4 + 255) / 256, 256>>>(x, total4);

    dim3 grid(CTAS_X, K);
    sparse_conv_mma7<<<grid, THREADS, SM_TOTAL>>>(W, in_map, out_map, out, M);
}